// round 14
// baseline (speedup 1.0000x reference)
#include <cuda_runtime.h>
#include <math.h>

#ifndef M_PI
#define M_PI 3.14159265358979323846
#endif

// ---------------- problem sizes ----------------
#define BB   64      // batch
#define NCHS 10      // selected channels
#define TT   2000    // raw time length
#define PADL 21      // filtfilt pad
#define TE   (TT + 2*PADL)   // 2042 extended length
#define TEP  2112    // padded (prefetch overrun slack)
#define TR   1280    // resampled length
#define DM   16      // d_model
#define NROWS (BB*NCHS)      // 640
#define PF   32      // IIR prefetch depth (covers L2 latency)
#define CH   16      // IIR chunks per row
#define CL   128     // chunk length (last chunk = 122)
#define CLLOG 7      // log2(CL)

typedef unsigned long long u64;
typedef unsigned int u32;

__constant__ int d_CH[10] = {126,125,48,112,67,93,10,61,39,108};

// ---------------- scratch (static device globals; no runtime alloc) ----------------
__device__ float  g_mean[BB*TT];
__device__ float  g_extT[TEP*NROWS];
__device__ float  g_wrkT[TEP*NROWS];
__device__ float  g_yf [NROWS*TT];
__device__ float  g_es [CH][6][NROWS];
__device__ float  g_esb[CH][6][NROWS];
__device__ float  g_xr[NROWS*TR];
__device__ float  g_h0[BB*TR*DM];
__device__ float  g_q[BB*TR*DM];
__device__ float  g_k[BB*TR*DM];
__device__ float  g_v[BB*TR*DM];
__device__ float  g_pool[BB*DM];
__device__ float  g_pe[TR*DM];

// =====================================================================
// Compile-time (constexpr) filter constants
// =====================================================================
constexpr double PI_D = 3.141592653589793238462643383279502884;

constexpr double c_red(double x) {
    double y = x;
    while (y >  PI_D) y -= 2.0 * PI_D;
    while (y < -PI_D) y += 2.0 * PI_D;
    return y;
}
constexpr double c_sin(double x) {
    double y = c_red(x);
    double y2 = y * y, t = y, s = y;
    for (int k = 1; k <= 26; k++) { t *= -y2 / ((2.0 * k) * (2.0 * k + 1.0)); s += t; }
    return s;
}
constexpr double c_cos(double x) {
    double y = c_red(x);
    double y2 = y * y, t = 1.0, s = 1.0;
    for (int k = 1; k <= 26; k++) { t *= -y2 / ((2.0 * k - 1.0) * (2.0 * k)); s += t; }
    return s;
}
constexpr double c_tan(double x) { return c_sin(x) / c_cos(x); }
constexpr double c_sqrt(double x) {
    if (x <= 0.0) return 0.0;
    double g = (x > 1.0) ? x : 1.0;
    for (int i = 0; i < 80; i++) g = 0.5 * (g + x / g);
    return g;
}
constexpr double c_i0(double x) {
    double s = 1.0, t = 1.0;
    double x2 = x * x * 0.25;
    for (int k = 1; k < 60; k++) {
        t *= x2 / ((double)k * (double)k);
        s += t;
        if (t < s * 1e-18) break;
    }
    return s;
}

struct Fir { float h[526]; };
constexpr Fir make_fir() {
    double ht[501] = {};
    double i0b = c_i0(5.0);
    for (int n = 0; n < 501; n++) {
        double mm  = (double)n - 250.0;
        double fc  = 1.0 / 25.0;
        double xx  = fc * mm;
        double snc = (n == 250) ? 1.0 : (c_sin(PI_D * xx) / (PI_D * xx));
        double r   = mm / 250.0;
        double arg = 1.0 - r * r;
        double w   = c_i0(5.0 * c_sqrt(arg < 0.0 ? 0.0 : arg)) / i0b;
        ht[n] = fc * snc * w;
    }
    double s = 0.0;
    for (int n = 0; n < 501; n++) s += ht[n];
    Fir F{};
    for (int i = 0; i < 25; i++) F.h[i] = 0.0f;
    for (int n = 0; n < 501; n++) F.h[25 + n] = (float)(ht[n] / s * 16.0);
    return F;
}
__device__ const Fir g_fir = make_fir();

struct CoefD { double b[3][3]; double a[3][2]; double zi[3][2]; };
constexpr CoefD make_coefd() {
    double warped = 4.0 * c_tan(PI_D * 0.01 / 2.0);
    double pr[6] = {}, pim[6] = {};
    for (int i = 0; i < 6; i++) {
        int m = -5 + 2 * i;
        double th = PI_D * (double)m / 12.0;
        double ar = -c_cos(th), ai = -c_sin(th);
        double den = ar * ar + ai * ai;
        pr[i]  =  warped * ar / den;
        pim[i] = -warped * ai / den;
    }
    double qr = 1.0, qi = 0.0;
    for (int i = 0; i < 6; i++) {
        double xr = 4.0 - pr[i], xi = -pim[i];
        double nr = qr * xr - qi * xi;
        double ni = qr * xi + qi * xr;
        qr = nr; qi = ni;
    }
    double kk = 4096.0 * qr / (qr * qr + qi * qi);
    double dr[6] = {}, di[6] = {};
    for (int i = 0; i < 6; i++) {
        double nr = 4.0 + pr[i], ni = pim[i];
        double mr = 4.0 - pr[i], mi = -pim[i];
        double dd = mr * mr + mi * mi;
        dr[i] = (nr * mr + ni * mi) / dd;
        di[i] = (ni * mr - nr * mi) / dd;
    }
    double sr[3] = {}, si[3] = {}; int c = 0;
    for (int i = 0; i < 6; i++) if (di[i] > 0.0) { sr[c] = dr[i]; si[c] = di[i]; c++; }
    double key[3] = {};
    for (int i = 0; i < 3; i++) {
        double mag = c_sqrt(sr[i] * sr[i] + si[i] * si[i]);
        double dv = mag - 1.0;
        key[i] = dv < 0.0 ? -dv : dv;
    }
    int ord[3] = {0, 1, 2};
    for (int a = 0; a < 3; a++)
        for (int b = a + 1; b < 3; b++)
            if (key[ord[b]] > key[ord[a]]) { int t = ord[a]; ord[a] = ord[b]; ord[b] = t; }
    CoefD C{};
    double zs = 1.0;
    for (int s2 = 0; s2 < 3; s2++) {
        int i = ord[s2];
        double b0 = (s2 == 0) ? kk : 1.0;
        double b1 = -2.0 * b0, b2 = b0;
        double a1 = -2.0 * sr[i];
        double a2 = sr[i] * sr[i] + si[i] * si[i];
        C.b[s2][0] = b0; C.b[s2][1] = b1; C.b[s2][2] = b2;
        C.a[s2][0] = a1; C.a[s2][1] = a2;
        double det = 1.0 + a1 + a2;
        double B0 = b1 - a1 * b0, B1 = b2 - a2 * b0;
        double z0 = (B0 + B1) / det;
        double z1 = (-a2 * B0 + (1.0 + a1) * B1) / det;
        C.zi[s2][0] = zs * z0;
        C.zi[s2][1] = zs * z1;
        zs *= (b0 + b1 + b2) / det;
    }
    return C;
}
constexpr CoefD KD = make_coefd();

constexpr float KB00=(float)KD.b[0][0], KB01=(float)KD.b[0][1], KB02=(float)KD.b[0][2];
constexpr float KB10=(float)KD.b[1][0], KB11=(float)KD.b[1][1], KB12=(float)KD.b[1][2];
constexpr float KB20=(float)KD.b[2][0], KB21=(float)KD.b[2][1], KB22=(float)KD.b[2][2];
constexpr float KA01=(float)KD.a[0][0], KA02=(float)KD.a[0][1];
constexpr float KA11=(float)KD.a[1][0], KA12=(float)KD.a[1][1];
constexpr float KA21=(float)KD.a[2][0], KA22=(float)KD.a[2][1];
constexpr float KZ00=(float)KD.zi[0][0], KZ01=(float)KD.zi[0][1];
constexpr float KZ10=(float)KD.zi[1][0], KZ11=(float)KD.zi[1][1];
constexpr float KZ20=(float)KD.zi[2][0], KZ21=(float)KD.zi[2][1];

struct StepR { double s[6]; double y; };
constexpr StepR ss_step(const double* s, double v) {
    double y0  = KD.b[0][0]*v + s[0];
    double z00 = KD.b[0][1]*v - KD.a[0][0]*y0 + s[1];
    double z01 = KD.b[0][2]*v - KD.a[0][1]*y0;
    double y1  = KD.b[1][0]*y0 + s[2];
    double z10 = KD.b[1][1]*y0 - KD.a[1][0]*y1 + s[3];
    double z11 = KD.b[1][2]*y0 - KD.a[1][1]*y1;
    double y2  = KD.b[2][0]*y1 + s[4];
    double z20 = KD.b[2][1]*y1 - KD.a[2][0]*y2 + s[5];
    double z21 = KD.b[2][2]*y1 - KD.a[2][1]*y2;
    return StepR{{z00,z01,z10,z11,z20,z21}, y2};
}
struct Tables { float ACL[6][6]; };
constexpr Tables make_tables() {
    double P[6][6] = {};
    for (int j = 0; j < 6; j++) {
        double e[6] = {}; e[j] = 1.0;
        StepR r = ss_step(e, 0.0);
        for (int i = 0; i < 6; i++) P[i][j] = r.s[i];
    }
    for (int k = 0; k < CLLOG; k++) {      // A -> A^CL
        double Q[6][6] = {};
        for (int i = 0; i < 6; i++)
            for (int l = 0; l < 6; l++) {
                double acc = 0.0;
                for (int j = 0; j < 6; j++) acc += P[i][j] * P[j][l];
                Q[i][l] = acc;
            }
        for (int i = 0; i < 6; i++) for (int l = 0; l < 6; l++) P[i][l] = Q[i][l];
    }
    Tables T{};
    for (int i = 0; i < 6; i++) for (int j = 0; j < 6; j++) T.ACL[i][j] = (float)P[i][j];
    return T;
}
constexpr Tables TB = make_tables();
#define TBA(i,j) (TB.ACL[i][j])

// ---------------- small asm helpers ----------------
__device__ __forceinline__ u32 hpack(float lo, float hi) {
    u32 d; asm("cvt.rn.f16x2.f32 %0, %1, %2;" : "=r"(d) : "f"(hi), "f"(lo)); return d;
}
__device__ __forceinline__ u32 ex2h2(u32 x) {
    u32 y; asm("ex2.approx.f16x2 %0, %1;" : "=r"(y) : "r"(x)); return y;
}

#define MMA_F16(c, a, b0_, b1_)                                                         \
    asm("mma.sync.aligned.m16n8k16.row.col.f32.f16.f16.f32 "                            \
        "{%0,%1,%2,%3},{%4,%5,%6,%7},{%8,%9},{%0,%1,%2,%3};"                            \
        : "+f"((c)[0]), "+f"((c)[1]), "+f"((c)[2]), "+f"((c)[3])                        \
        : "r"((a)[0]), "r"((a)[1]), "r"((a)[2]), "r"((a)[3]), "r"(b0_), "r"(b1_))

// ---------------- init: PE table + pool zero ----------------
__global__ void eeg_init_pe_kernel() {
    int e = blockIdx.x * blockDim.x + threadIdx.x;
    if (e < TR * DM) {
        int pos = e / DM, d = e % DM;
        double div = exp(-((double)(d & ~1)) * log(10000.0) / 16.0);
        double ang = (double)pos * div;
        g_pe[e] = (float)((d & 1) ? cos(ang) : sin(ang));
    }
    if (e < BB * DM) g_pool[e] = 0.f;
}

// ---------------- stage 1: mean over selected channels ----------------
__global__ void eeg_mean_kernel(const float* __restrict__ x) {
    int idx = blockIdx.x * blockDim.x + threadIdx.x;
    if (idx >= BB * TT) return;
    int b = idx / TT, t = idx % TT;
    float s = 0.f;
    #pragma unroll
    for (int c = 0; c < 10; c++) s += x[((long)(b * 128 + d_CH[c])) * TT + t];
    g_mean[idx] = s * (1.0f / 10.0f);
}

// ---------------- stage 1b: build extended, padded, TRANSPOSED signal ----------------
__global__ void eeg_buildext_kernel(const float* __restrict__ x) {
    int idx = blockIdx.x * blockDim.x + threadIdx.x;
    if (idx >= TE * NROWS) return;
    int t = idx / NROWS, row = idx % NROWS;
    int b = row / NCHS, c = row % NCHS;
    const float* xp = x + ((long)(b * 128 + d_CH[c])) * TT;
    const float* mp = g_mean + (long)b * TT;
    float v;
    if (t < PADL) {
        float c0 = xp[0] - mp[0];
        int j = PADL - t;
        v = 2.f * c0 - (xp[j] - mp[j]);
    } else if (t < PADL + TT) {
        int j = t - PADL;
        v = xp[j] - mp[j];
    } else {
        float cl = xp[TT - 1] - mp[TT - 1];
        int j = 1998 - (t - (PADL + TT));
        v = 2.f * cl - (xp[j] - mp[j]);
    }
    g_extT[idx] = v;
}

// ---------------- biquad step (immediate coefficients) ----------------
#define BQ_IMM(v, y2out)                                   \
    {                                                      \
        float y0 = fmaf(KB00, (v), z00);                   \
        z00 = fmaf(-KA01, y0, fmaf(KB01, (v), z01));       \
        z01 = fmaf(-KA02, y0, KB02 * (v));                 \
        float y1 = fmaf(KB10, y0, z10);                    \
        z10 = fmaf(-KA11, y1, fmaf(KB11, y0, z11));        \
        z11 = fmaf(-KA12, y1, KB12 * y0);                  \
        y2out = fmaf(KB20, y1, z20);                       \
        z20 = fmaf(-KA21, y2out, fmaf(KB21, y1, z21));     \
        z21 = fmaf(-KA22, y2out, KB22 * y1);               \
    }

#define BQH_IMM(y2out)                                     \
    {                                                      \
        float y0 = z00;                                    \
        z00 = fmaf(-KA01, y0, z01);                        \
        z01 = -KA02 * y0;                                  \
        float y1 = fmaf(KB10, y0, z10);                    \
        z10 = fmaf(-KA11, y1, fmaf(KB11, y0, z11));        \
        z11 = fmaf(-KA12, y1, KB12 * y0);                  \
        y2out = fmaf(KB20, y1, z20);                       \
        z20 = fmaf(-KA21, y2out, fmaf(KB21, y1, z21));     \
        z21 = fmaf(-KA22, y2out, KB22 * y1);               \
    }

// ---------------- stage 2a: fwd phase A ----------------
__global__ void __launch_bounds__(32, 1) eeg_fA_kernel() {
    int row = blockIdx.x * 32 + threadIdx.x;
    int c = blockIdx.y;
    int base = c * CL;
    int Lc = (c == CH - 1) ? (TE - (CH - 1) * CL) : CL;
    float z00, z01, z10, z11, z20, z21;
    if (c == 0) {
        float x0 = g_extT[row];
        z00 = KZ00 * x0; z01 = KZ01 * x0;
        z10 = KZ10 * x0; z11 = KZ11 * x0;
        z20 = KZ20 * x0; z21 = KZ21 * x0;
    } else {
        z00 = z01 = z10 = z11 = z20 = z21 = 0.f;
    }
    const float* src = g_extT + row;
    float* dst = g_wrkT + row;
    float bufA[PF], bufB[PF];
    #pragma unroll
    for (int i = 0; i < PF; i++) bufA[i] = src[(base + i) * NROWS];
    int nblk = Lc / PF;
    int t0 = base;
    for (int blk = 0; blk < nblk; blk++, t0 += PF) {
        #pragma unroll
        for (int i = 0; i < PF; i++) bufB[i] = src[(t0 + PF + i) * NROWS];
        #pragma unroll
        for (int i = 0; i < PF; i++) { float y2; BQ_IMM(bufA[i], y2); dst[(t0 + i) * NROWS] = y2; }
        #pragma unroll
        for (int i = 0; i < PF; i++) bufA[i] = bufB[i];
    }
    for (int i = 0; i < Lc - nblk * PF; i++) { float y2; BQ_IMM(bufA[i], y2); dst[(t0 + i) * NROWS] = y2; }
    if (c < CH - 1) {
        g_es[c][0][row] = z00; g_es[c][1][row] = z01; g_es[c][2][row] = z10;
        g_es[c][3][row] = z11; g_es[c][4][row] = z20; g_es[c][5][row] = z21;
    }
}

// ---------------- state propagation helper ----------------
#define PROPAGATE(ES)                                                                            \
    float s0 = ES[0][0][row], s1 = ES[0][1][row], s2 = ES[0][2][row];                            \
    float s3 = ES[0][3][row], s4 = ES[0][4][row], s5 = ES[0][5][row];                            \
    for (int i = 1; i < c; i++) {                                                                \
        float e0 = ES[i][0][row], e1 = ES[i][1][row], e2 = ES[i][2][row];                        \
        float e3 = ES[i][3][row], e4 = ES[i][4][row], e5 = ES[i][5][row];                        \
        float n0 = fmaf(TBA(0,0),s0, fmaf(TBA(0,1),s1, fmaf(TBA(0,2),s2, fmaf(TBA(0,3),s3, fmaf(TBA(0,4),s4, fmaf(TBA(0,5),s5, e0)))))); \
        float n1 = fmaf(TBA(1,0),s0, fmaf(TBA(1,1),s1, fmaf(TBA(1,2),s2, fmaf(TBA(1,3),s3, fmaf(TBA(1,4),s4, fmaf(TBA(1,5),s5, e1)))))); \
        float n2 = fmaf(TBA(2,0),s0, fmaf(TBA(2,1),s1, fmaf(TBA(2,2),s2, fmaf(TBA(2,3),s3, fmaf(TBA(2,4),s4, fmaf(TBA(2,5),s5, e2)))))); \
        float n3 = fmaf(TBA(3,0),s0, fmaf(TBA(3,1),s1, fmaf(TBA(3,2),s2, fmaf(TBA(3,3),s3, fmaf(TBA(3,4),s4, fmaf(TBA(3,5),s5, e3)))))); \
        float n4 = fmaf(TBA(4,0),s0, fmaf(TBA(4,1),s1, fmaf(TBA(4,2),s2, fmaf(TBA(4,3),s3, fmaf(TBA(4,4),s4, fmaf(TBA(4,5),s5, e4)))))); \
        float n5 = fmaf(TBA(5,0),s0, fmaf(TBA(5,1),s1, fmaf(TBA(5,2),s2, fmaf(TBA(5,3),s3, fmaf(TBA(5,4),s4, fmaf(TBA(5,5),s5, e5)))))); \
        s0 = n0; s1 = n1; s2 = n2; s3 = n3; s4 = n4; s5 = n5;                                    \
    }

// ---------------- stage 2b: fwd phase C ----------------
__global__ void __launch_bounds__(32, 1) eeg_fC_kernel() {
    int row = blockIdx.x * 32 + threadIdx.x;
    int c = blockIdx.y + 1;
    PROPAGATE(g_es);
    float z00 = s0, z01 = s1, z10 = s2, z11 = s3, z20 = s4, z21 = s5;
    int base = c * CL;
    int Lc = (c == CH - 1) ? (TE - (CH - 1) * CL) : CL;
    float* p = g_wrkT + row;
    float bufA[PF], bufB[PF];
    #pragma unroll
    for (int i = 0; i < PF; i++) bufA[i] = p[(base + i) * NROWS];
    int nblk = Lc / PF;
    int t0 = base;
    for (int blk = 0; blk < nblk; blk++, t0 += PF) {
        #pragma unroll
        for (int i = 0; i < PF; i++) bufB[i] = p[(t0 + PF + i) * NROWS];
        #pragma unroll
        for (int i = 0; i < PF; i++) { float yh; BQH_IMM(yh); p[(t0 + i) * NROWS] = bufA[i] + yh; }
        #pragma unroll
        for (int i = 0; i < PF; i++) bufA[i] = bufB[i];
    }
    for (int i = 0; i < Lc - nblk * PF; i++) { float yh; BQH_IMM(yh); p[(t0 + i) * NROWS] = bufA[i] + yh; }
}

// ---------------- stage 2c: bwd phase A ----------------
__global__ void __launch_bounds__(32, 1) eeg_bA_kernel() {
    int row = blockIdx.x * 32 + threadIdx.x;
    int c = blockIdx.y;
    int base = c * CL;
    int Lc = (c == CH - 1) ? (TE - (CH - 1) * CL) : CL;
    float z00, z01, z10, z11, z20, z21;
    if (c == 0) {
        float x0 = g_wrkT[(TE - 1) * NROWS + row];
        z00 = KZ00 * x0; z01 = KZ01 * x0;
        z10 = KZ10 * x0; z11 = KZ11 * x0;
        z20 = KZ20 * x0; z21 = KZ21 * x0;
    } else {
        z00 = z01 = z10 = z11 = z20 = z21 = 0.f;
    }
    const float* src = g_wrkT + row;
    float* yrow = g_yf + (long)row * TT;
    float bufA[PF], bufB[PF];
    #pragma unroll
    for (int i = 0; i < PF; i++) {
        int s = TE - 1 - (base + i);
        bufA[i] = src[((s > 0) ? s : 0) * NROWS];
    }
    int nblk = Lc / PF;
    int t0 = base;
    for (int blk = 0; blk < nblk; blk++, t0 += PF) {
        #pragma unroll
        for (int i = 0; i < PF; i++) {
            int s = TE - 1 - (t0 + PF + i);
            bufB[i] = src[((s > 0) ? s : 0) * NROWS];
        }
        #pragma unroll
        for (int i = 0; i < PF; i++) {
            float y2; BQ_IMM(bufA[i], y2);
            int rt = t0 + i;
            if (c == 0) {
                int tau = 2020 - rt;
                if (tau < TT) yrow[tau] = y2;
            } else {
                g_extT[rt * NROWS + row] = y2;
            }
        }
        #pragma unroll
        for (int i = 0; i < PF; i++) bufA[i] = bufB[i];
    }
    for (int i = 0; i < Lc - nblk * PF; i++) {
        float y2; BQ_IMM(bufA[i], y2);
        int rt = t0 + i;
        if (c == 0) {
            int tau = 2020 - rt;
            if (tau < TT) yrow[tau] = y2;
        } else {
            g_extT[rt * NROWS + row] = y2;
        }
    }
    if (c < CH - 1) {
        g_esb[c][0][row] = z00; g_esb[c][1][row] = z01; g_esb[c][2][row] = z10;
        g_esb[c][3][row] = z11; g_esb[c][4][row] = z20; g_esb[c][5][row] = z21;
    }
}

// ---------------- stage 2d: bwd phase C ----------------
__global__ void __launch_bounds__(32, 1) eeg_bC_kernel() {
    int row = blockIdx.x * 32 + threadIdx.x;
    int c = blockIdx.y + 1;
    PROPAGATE(g_esb);
    float z00 = s0, z01 = s1, z10 = s2, z11 = s3, z20 = s4, z21 = s5;
    int base = c * CL;
    int Lc = (c == CH - 1) ? (TE - (CH - 1) * CL) : CL;
    const float* p = g_extT + row;
    float* yrow = g_yf + (long)row * TT;
    float bufA[PF], bufB[PF];
    #pragma unroll
    for (int i = 0; i < PF; i++) bufA[i] = p[(base + i) * NROWS];
    int nblk = Lc / PF;
    int t0 = base;
    for (int blk = 0; blk < nblk; blk++, t0 += PF) {
        #pragma unroll
        for (int i = 0; i < PF; i++) bufB[i] = p[(t0 + PF + i) * NROWS];
        #pragma unroll
        for (int i = 0; i < PF; i++) {
            float yh; BQH_IMM(yh);
            int tau = 2020 - (t0 + i);
            if (tau >= 0) yrow[tau] = bufA[i] + yh;
        }
        #pragma unroll
        for (int i = 0; i < PF; i++) bufA[i] = bufB[i];
    }
    for (int i = 0; i < Lc - nblk * PF; i++) {
        float yh; BQH_IMM(yh);
        int tau = 2020 - (t0 + i);
        if (tau >= 0) yrow[tau] = bufA[i] + yh;
    }
}

// ---------------- stage 3: polyphase resample + tanh + per-row standardize ----------------
__global__ void eeg_resample_kernel() {
    __shared__ float yf[TT];
    __shared__ float tv[TR];
    __shared__ float hh[526];
    __shared__ float red[256];
    int row = blockIdx.x, tid = threadIdx.x;
    const float* src = g_yf + (long)row * TT;
    for (int t = tid; t < TT; t += 256) yf[t] = src[t];
    for (int i = tid; i < 526; i += 256) hh[i] = g_fir.h[i];
    __syncthreads();
    for (int n = tid; n < TR; n += 256) {
        int A = (n + 11) * 25;
        int tlo = A - 525 + 15;
        tlo = (tlo > 0) ? (tlo >> 4) : 0;
        int thi = A >> 4;
        if (thi > TT - 1) thi = TT - 1;
        float s0 = 0.f, s1 = 0.f, s2 = 0.f, s3 = 0.f;
        int t = tlo, idx = A - 16 * tlo;
        for (; t + 3 <= thi; t += 4, idx -= 64) {
            s0 = fmaf(yf[t],     hh[idx],      s0);
            s1 = fmaf(yf[t + 1], hh[idx - 16], s1);
            s2 = fmaf(yf[t + 2], hh[idx - 32], s2);
            s3 = fmaf(yf[t + 3], hh[idx - 48], s3);
        }
        for (; t <= thi; t++, idx -= 16) s0 = fmaf(yf[t], hh[idx], s0);
        tv[n] = tanhf((s0 + s1) + (s2 + s3));
    }
    __syncthreads();
    float ls = 0.f;
    for (int n = tid; n < TR; n += 256) ls += tv[n];
    red[tid] = ls; __syncthreads();
    for (int st = 128; st > 0; st >>= 1) { if (tid < st) red[tid] += red[tid + st]; __syncthreads(); }
    float mean = red[0] * (1.f / TR);
    __syncthreads();
    float lv = 0.f;
    for (int n = tid; n < TR; n += 256) { float d = tv[n] - mean; lv = fmaf(d, d, lv); }
    red[tid] = lv; __syncthreads();
    for (int st = 128; st > 0; st >>= 1) { if (tid < st) red[tid] += red[tid + st]; __syncthreads(); }
    float var  = red[0] * (1.f / (TR - 1));
    float stdv = fmaxf(sqrtf(var), 1e-6f);
    float inv  = 1.f / stdv;
    float* dst = g_xr + (long)row * TR;
    for (int n = tid; n < TR; n += 256) dst[n] = (tv[n] - mean) * inv;
}

// ---------------- stage 4+5 fused: conv1d + relu + LN0 + PE + QKV ----------------
__global__ void eeg_convqkv_kernel(const float* __restrict__ cw, const float* __restrict__ cb,
                                   const float* __restrict__ ln0g, const float* __restrict__ ln0b,
                                   const float* __restrict__ wqkv, const float* __restrict__ bqkv) {
    __shared__ float w[480];
    __shared__ float bias[16], sg[16], sb[16];
    __shared__ float wq[768];
    __shared__ float bq[48];
    int tid = threadIdx.x;
    for (int i = tid; i < 480; i += blockDim.x) w[i] = cw[i];
    for (int i = tid; i < 768; i += blockDim.x) wq[i] = wqkv[i];
    if (tid < 16) { bias[tid] = cb[tid]; sg[tid] = ln0g[tid]; sb[tid] = ln0b[tid]; }
    if (tid < 48) bq[tid] = bqkv[tid];
    __syncthreads();
    int idx = blockIdx.x * blockDim.x + tid;   // b*TR + n
    if (idx >= BB * TR) return;
    int b = idx / TR, n = idx % TR;
    float xin[10][3];
    #pragma unroll
    for (int i = 0; i < 10; i++) {
        const float* base = g_xr + ((long)b * NCHS + i) * TR + n;
        xin[i][0] = (n > 0)      ? base[-1] : 0.f;
        xin[i][1] = base[0];
        xin[i][2] = (n < TR - 1) ? base[1]  : 0.f;
    }
    float o[16];
    #pragma unroll
    for (int oc = 0; oc < 16; oc++) {
        float s = bias[oc];
        #pragma unroll
        for (int i = 0; i < 10; i++) {
            s = fmaf(w[oc * 30 + i * 3 + 0], xin[i][0], s);
            s = fmaf(w[oc * 30 + i * 3 + 1], xin[i][1], s);
            s = fmaf(w[oc * 30 + i * 3 + 2], xin[i][2], s);
        }
        o[oc] = fmaxf(s, 0.f);
    }
    float mu = 0.f;
    #pragma unroll
    for (int d = 0; d < 16; d++) mu += o[d];
    mu *= (1.f / 16);
    float var = 0.f;
    #pragma unroll
    for (int d = 0; d < 16; d++) { float dd = o[d] - mu; var = fmaf(dd, dd, var); }
    var *= (1.f / 16);
    float r = rsqrtf(var + 1e-5f);
    float xv[16];
    const float* pe = g_pe + n * 16;
    float* dst = g_h0 + (long)idx * 16;
    #pragma unroll
    for (int d = 0; d < 16; d++) {
        xv[d] = fmaf((o[d] - mu) * r, sg[d], sb[d]) + pe[d];
        dst[d] = xv[d];
    }
    float* qd = g_q + (long)idx * 16;
    float* kd = g_k + (long)idx * 16;
    float* vd = g_v + (long)idx * 16;
    const float QSCALE = 0.25f * 1.4426950408889634f;
    #pragma unroll
    for (int j = 0; j < 16; j++) {
        float sq = bq[j], sk = bq[16 + j], sv = bq[32 + j];
        #pragma unroll
        for (int d = 0; d < 16; d++) {
            sq = fmaf(wq[j * 16 + d],        xv[d], sq);
            sk = fmaf(wq[(16 + j) * 16 + d], xv[d], sk);
            sv = fmaf(wq[(32 + j) * 16 + d], xv[d], sv);
        }
        qd[j] = sq * QSCALE;
        kd[j] = sk;
        vd[j] = sv;
    }
}

// ---------------- LN helper ----------------
__device__ __forceinline__ void ln16(float* v, const float* g, const float* b) {
    float mu = 0.f;
    #pragma unroll
    for (int d = 0; d < 16; d++) mu += v[d];
    mu *= (1.f / 16);
    float var = 0.f;
    #pragma unroll
    for (int d = 0; d < 16; d++) { float dd = v[d] - mu; var = fmaf(dd, dd, var); }
    var *= (1.f / 16);
    float r = rsqrtf(var + 1e-5f);
    #pragma unroll
    for (int d = 0; d < 16; d++) v[d] = fmaf((v[d] - mu) * r, g[d], b[d]);
}

// =====================================================================
// stage 6: tensor-core flash attention (fp16 QK + fp16 PV, ex2.f16x2)
// block = 128 threads = 4 warps; warp w owns query rows 32w..32w+31
// =====================================================================
__global__ void __launch_bounds__(128) eeg_attn_kernel(
                                const float* __restrict__ wo, const float* __restrict__ bo,
                                const float* __restrict__ w1, const float* __restrict__ b1,
                                const float* __restrict__ w2, const float* __restrict__ b2,
                                const float* __restrict__ l1g, const float* __restrict__ l1b,
                                const float* __restrict__ l2g, const float* __restrict__ l2b) {
    __shared__ float smemA[2176];       // KTH fp16 tile (8 x 132 u32) / later ovs (128 x 17)
    __shared__ u32   vp[64 * 24];       // V f16x2 pairs: [pair][dim24] (dim16 = ones)
    __shared__ float swo[256], sbo[16], sw1[512], sb1[32], sw2[512], sb2[16];
    __shared__ float sl1g[16], sl1b[16], sl2g[16], sl2b[16];
    u32* KTH = (u32*)smemA;             // [dimpair 0..7][key 0..127], stride 132
    int tid = threadIdx.x;
    int lane = tid & 31, w = tid >> 5;
    int g = lane >> 2, qd4 = lane & 3;

    for (int i = tid; i < 256; i += 128) swo[i] = wo[i];
    for (int i = tid; i < 512; i += 128) { sw1[i] = w1[i]; sw2[i] = w2[i]; }
    if (tid < 16) {
        sbo[tid] = bo[tid]; sb2[tid] = b2[tid];
        sl1g[tid] = l1g[tid]; sl1b[tid] = l1b[tid];
        sl2g[tid] = l2g[tid]; sl2b[tid] = l2b[tid];
    }
    if (tid < 32) sb1[tid] = b1[tid];

    int b = blockIdx.x / 10, qt = blockIdx.x % 10;
    long bTR = (long)b * TR;
    int qrow0 = qt * 128;

    // ---- Q A-fragments (m16n8k16 fp16 layout), loaded once ----
    u32 qh[2][4];
    #pragma unroll
    for (int m = 0; m < 2; m++) {
        const float* qp = g_q + (bTR + qrow0 + 32 * w + 16 * m + g) * 16;
        qh[m][0] = hpack(qp[2 * qd4],           qp[2 * qd4 + 1]);
        qh[m][1] = hpack(qp[128 + 2 * qd4],     qp[128 + 2 * qd4 + 1]);   // row+8
        qh[m][2] = hpack(qp[2 * qd4 + 8],       qp[2 * qd4 + 9]);
        qh[m][3] = hpack(qp[128 + 2 * qd4 + 8], qp[128 + 2 * qd4 + 9]);
    }

    // ---- O accumulators: 2 m-tiles x 3 n8 dim-tiles (dims 0-7, 8-15, 16-23) ----
    float oc[2][3][4];
    #pragma unroll
    for (int m = 0; m < 2; m++)
        #pragma unroll
        for (int dt = 0; dt < 3; dt++)
            #pragma unroll
            for (int e = 0; e < 4; e++) oc[m][dt][e] = 0.f;

    for (int kb = 0; kb < 10; kb++) {
        __syncthreads();
        // stage K as fp16 pairs [dimpair][key] (stride 132)
        {
            const float4* kp = (const float4*)(g_k + (bTR + kb * 128 + tid) * 16);
            float4 r0 = kp[0], r1 = kp[1], r2 = kp[2], r3 = kp[3];
            KTH[0 * 132 + tid] = hpack(r0.x, r0.y);
            KTH[1 * 132 + tid] = hpack(r0.z, r0.w);
            KTH[2 * 132 + tid] = hpack(r1.x, r1.y);
            KTH[3 * 132 + tid] = hpack(r1.z, r1.w);
            KTH[4 * 132 + tid] = hpack(r2.x, r2.y);
            KTH[5 * 132 + tid] = hpack(r2.z, r2.w);
            KTH[6 * 132 + tid] = hpack(r3.x, r3.y);
            KTH[7 * 132 + tid] = hpack(r3.z, r3.w);
        }
        // stage V as f16x2 key-pairs [pair][dim], + ones/zero columns
        if (tid < 64) {
            const float4* v0 = (const float4*)(g_v + (bTR + kb * 128 + 2 * tid) * 16);
            float4 a0 = v0[0], a1 = v0[1], a2 = v0[2], a3 = v0[3];
            float4 b0_ = v0[4], b1_ = v0[5], b2_ = v0[6], b3_ = v0[7];
            u32* vd = vp + tid * 24;
            vd[0]  = hpack(a0.x, b0_.x); vd[1]  = hpack(a0.y, b0_.y);
            vd[2]  = hpack(a0.z, b0_.z); vd[3]  = hpack(a0.w, b0_.w);
            vd[4]  = hpack(a1.x, b1_.x); vd[5]  = hpack(a1.y, b1_.y);
            vd[6]  = hpack(a1.z, b1_.z); vd[7]  = hpack(a1.w, b1_.w);
            vd[8]  = hpack(a2.x, b2_.x); vd[9]  = hpack(a2.y, b2_.y);
            vd[10] = hpack(a2.z, b2_.z); vd[11] = hpack(a2.w, b2_.w);
            vd[12] = hpack(a3.x, b3_.x); vd[13] = hpack(a3.y, b3_.y);
            vd[14] = hpack(a3.z, b3_.z); vd[15] = hpack(a3.w, b3_.w);
        } else {
            u32* vd = vp + (tid - 64) * 24;
            vd[16] = 0x3C003C00u;   // ones column (fp16 1.0, 1.0)
            #pragma unroll
            for (int d = 17; d < 24; d++) vd[d] = 0u;
        }
        __syncthreads();

        #pragma unroll 1
        for (int np = 0; np < 8; np++) {
            // ---- S fragments for 16 keys (two n8 blocks), fp16 k16 MMA ----
            float sc[2][2][4];
            #pragma unroll
            for (int m = 0; m < 2; m++)
                #pragma unroll
                for (int nb = 0; nb < 2; nb++)
                    #pragma unroll
                    for (int e = 0; e < 4; e++) sc[m][nb][e] = 0.f;
            #pragma unroll
            for (int nb = 0; nb < 2; nb++) {
                int key0 = 16 * np + 8 * nb + g;
                u32 kb0 = KTH[qd4 * 132 + key0];
                u32 kb1 = KTH[(qd4 + 4) * 132 + key0];
                #pragma unroll
                for (int m = 0; m < 2; m++) MMA_F16(sc[m][nb], qh[m], kb0, kb1);
            }
            // ---- p = 2^s in packed fp16, direct A-frags ----
            u32 pa[2][4];
            #pragma unroll
            for (int m = 0; m < 2; m++) {
                pa[m][0] = ex2h2(hpack(sc[m][0][0], sc[m][0][1]));
                pa[m][1] = ex2h2(hpack(sc[m][0][2], sc[m][0][3]));
                pa[m][2] = ex2h2(hpack(sc[m][1][0], sc[m][1][1]));
                pa[m][3] = ex2h2(hpack(sc[m][1][2], sc[m][1][3]));
            }
            // ---- PV: 3 dim-tiles (incl. ones column for l) ----
            #pragma unroll
            for (int dt = 0; dt < 3; dt++) {
                u32 vb0 = vp[(8 * np + qd4) * 24 + dt * 8 + g];
                u32 vb1 = vp[(8 * np + 4 + qd4) * 24 + dt * 8 + g];
                #pragma unroll
                for (int m = 0; m < 2; m++) MMA_F16(oc[m][dt], pa[m], vb0, vb1);
            }
        }
    }
    __syncthreads();   // done with KTH; reuse as ovs

    // ---- normalize by l (ones column, col 16 -> lane%4==0) and write ovs ----
    float* ovs = smemA;
    #pragma unroll
    for (int m = 0; m < 2; m++) {
        float l0 = __shfl_sync(0xffffffffu, oc[m][2][0], lane & ~3);
        float l1 = __shfl_sync(0xffffffffu, oc[m][2][2], lane & ~3);
        float i0 = 1.f / l0, i1 = 1.f / l1;
        int r0 = 32 * w + 16 * m + g, r1 = r0 + 8;
        #pragma unroll
        for (int dt = 0; dt < 2; dt++) {
            int col = dt * 8 + 2 * qd4;
            ovs[r0 * 17 + col]     = oc[m][dt][0] * i0;
            ovs[r0 * 17 + col + 1] = oc[m][dt][1] * i0;
            ovs[r1 * 17 + col]     = oc[m][dt][2] * i1;
            ovs[r1 * 17 + col + 1] = oc[m][dt][3] * i1;
        }
    }
    __syncthreads();

    // ---- epilogue per query (tid) ----
    float ov[16];
    #pragma unroll
    for (int d = 0; d < 16; d++) ov[d] = ovs[tid * 17 + d];
    float h0v[16];
    {
        const float4* hs = (const float4*)(g_h0 + (bTR + qrow0 + tid) * 16);
        float4 a0 = hs[0], a1 = hs[1], a2 = hs[2], a3 = hs[3];
        h0v[0] = a0.x; h0v[1] = a0.y; h0v[2] = a0.z; h0v[3] = a0.w;
        h0v[4] = a1.x; h0v[5] = a1.y; h0v[6] = a1.z; h0v[7] = a1.w;
        h0v[8] = a2.x; h0v[9] = a2.y; h0v[10] = a2.z; h0v[11] = a2.w;
        h0v[12] = a3.x; h0v[13] = a3.y; h0v[14] = a3.z; h0v[15] = a3.w;
    }
    float x1[16];
    #pragma unroll
    for (int d = 0; d < 16; d++) {
        float s = sbo[d];
        #pragma unroll
        for (int e = 0; e < 16; e++) s = fmaf(swo[d * 16 + e], ov[e], s);
        x1[d] = h0v[d] + s;
    }
    ln16(x1, sl1g, sl1b);
    float f[16];
    #pragma unroll
    for (int d = 0; d < 16; d++) f[d] = sb2[d];
    #pragma unroll
    for (int j = 0; j < 32; j++) {
        float t = sb1[j];
        #pragma unroll
        for (int e = 0; e < 16; e++) t = fmaf(sw1[j * 16 + e], x1[e], t);
        t = fmaxf(t, 0.f);
        #pragma unroll
        for (int d = 0; d < 16; d++) f[d] = fmaf(sw2[d * 32 + j], t, f[d]);
    }
    float x2[16];
    #pragma unroll
    for (int d = 0; d < 16; d++) x2[d] = x1[d] + f[d];
    ln16(x2, sl2g, sl2b);
    __syncthreads();
    float* R = smemA;
    #pragma unroll
    for (int d = 0; d < 16; d++) R[tid * 16 + d] = x2[d];
    __syncthreads();
    for (int st = 64; st > 0; st >>= 1) {
        if (tid < st) {
            #pragma unroll
            for (int d = 0; d < 16; d++) R[tid * 16 + d] += R[(tid + st) * 16 + d];
        }
        __syncthreads();
    }
    if (tid < 16) atomicAdd(&g_pool[b * 16 + tid], R[tid]);
}

// ---------------- stage 7: head ----------------
__global__ void eeg_head_kernel(const float* __restrict__ wfc, const float* __restrict__ bfc,
                                float* __restrict__ out) {
    int b = threadIdx.x;
    if (b < BB) {
        float s = 0.f;
        #pragma unroll
        for (int d = 0; d < 16; d++) s = fmaf(g_pool[b * 16 + d], wfc[d], s);
        out[b] = s * (1.f / (float)TR) + bfc[0];
    }
}

// ---------------- launch ----------------
extern "C" void kernel_launch(void* const* d_in, const int* in_sizes, int n_in,
                              void* d_out, int out_size) {
    const float* x      = (const float*)d_in[0];
    const float* conv_w = (const float*)d_in[1];
    const float* conv_b = (const float*)d_in[2];
    const float* ln0g   = (const float*)d_in[3];
    const float* ln0b   = (const float*)d_in[4];
    const float* wqkv   = (const float*)d_in[5];
    const float* bqkv   = (const float*)d_in[6];
    const float* wo     = (const float*)d_in[7];
    const float* bo     = (const float*)d_in[8];
    const float* w1     = (const float*)d_in[9];
    const float* b1     = (const float*)d_in[10];
    const float* w2     = (const float*)d_in[11];
    const float* b2     = (const float*)d_in[12];
    const float* l1g    = (const float*)d_in[13];
    const float* l1b    = (const float*)d_in[14];
    const float* l2g    = (const float*)d_in[15];
    const float* l2b    = (const float*)d_in[16];
    const float* wfc    = (const float*)d_in[17];
    const float* bfc    = (const float*)d_in[18];
    float* out = (float*)d_out;

    eeg_init_pe_kernel<<<(TR * DM + 127) / 128, 128>>>();
    eeg_mean_kernel<<<(BB * TT + 255) / 256, 256>>>(x);
    eeg_buildext_kernel<<<(TE * NROWS + 255) / 256, 256>>>(x);
    eeg_fA_kernel<<<dim3(NROWS / 32, CH), 32>>>();
    eeg_fC_kernel<<<dim3(NROWS / 32, CH - 1), 32>>>();
    eeg_bA_kernel<<<dim3(NROWS / 32, CH), 32>>>();
    eeg_bC_kernel<<<dim3(NROWS / 32, CH - 1), 32>>>();
    eeg_resample_kernel<<<NROWS, 256>>>();
    eeg_convqkv_kernel<<<(BB * TR + 255) / 256, 256>>>(conv_w, conv_b, ln0g, ln0b, wqkv, bqkv);
    eeg_attn_kernel<<<NROWS, 128>>>(wo, bo, w1, b1, w2, b2, l1g, l1b, l2g, l2b);
    eeg_head_kernel<<<1, 64>>>(wfc, bfc, out);
}

// round 15
// speedup vs baseline: 1.5464x; 1.5464x over previous
#include <cuda_runtime.h>
#include <math.h>

#ifndef M_PI
#define M_PI 3.14159265358979323846
#endif

// ---------------- problem sizes ----------------
#define BB   64      // batch
#define NCHS 10      // selected channels
#define TT   2000    // raw time length
#define PADL 21      // filtfilt pad
#define TE   (TT + 2*PADL)   // 2042 extended length
#define TEP  2112    // padded (prefetch overrun slack)
#define TR   1280    // resampled length
#define DM   16      // d_model
#define NROWS (BB*NCHS)      // 640
#define PF   32      // IIR prefetch depth (covers L2 latency)
#define CH   16      // IIR chunks per row
#define CL   128     // chunk length (last chunk = 122)
#define CLLOG 7      // log2(CL)

typedef unsigned long long u64;
typedef unsigned int u32;

__constant__ int d_CH[10] = {126,125,48,112,67,93,10,61,39,108};

// ---------------- scratch (static device globals; no runtime alloc) ----------------
__device__ float  g_mean[BB*TT];
__device__ float  g_extT[TEP*NROWS];
__device__ float  g_wrkT[TEP*NROWS];
__device__ float  g_yf [NROWS*TT];
__device__ float  g_es [CH][6][NROWS];
__device__ float  g_esb[CH][6][NROWS];
__device__ float  g_xr[NROWS*TR];
__device__ float  g_h0[BB*TR*DM];
__device__ float  g_q[BB*TR*DM];
__device__ float  g_k[BB*TR*DM];
__device__ float  g_v[BB*TR*DM];
__device__ float  g_pool[BB*DM];
__device__ float  g_pe[TR*DM];

// =====================================================================
// Compile-time (constexpr) filter constants
// =====================================================================
constexpr double PI_D = 3.141592653589793238462643383279502884;

constexpr double c_red(double x) {
    double y = x;
    while (y >  PI_D) y -= 2.0 * PI_D;
    while (y < -PI_D) y += 2.0 * PI_D;
    return y;
}
constexpr double c_sin(double x) {
    double y = c_red(x);
    double y2 = y * y, t = y, s = y;
    for (int k = 1; k <= 26; k++) { t *= -y2 / ((2.0 * k) * (2.0 * k + 1.0)); s += t; }
    return s;
}
constexpr double c_cos(double x) {
    double y = c_red(x);
    double y2 = y * y, t = 1.0, s = 1.0;
    for (int k = 1; k <= 26; k++) { t *= -y2 / ((2.0 * k - 1.0) * (2.0 * k)); s += t; }
    return s;
}
constexpr double c_tan(double x) { return c_sin(x) / c_cos(x); }
constexpr double c_sqrt(double x) {
    if (x <= 0.0) return 0.0;
    double g = (x > 1.0) ? x : 1.0;
    for (int i = 0; i < 80; i++) g = 0.5 * (g + x / g);
    return g;
}
constexpr double c_i0(double x) {
    double s = 1.0, t = 1.0;
    double x2 = x * x * 0.25;
    for (int k = 1; k < 60; k++) {
        t *= x2 / ((double)k * (double)k);
        s += t;
        if (t < s * 1e-18) break;
    }
    return s;
}

struct Fir { float h[526]; };
constexpr Fir make_fir() {
    double ht[501] = {};
    double i0b = c_i0(5.0);
    for (int n = 0; n < 501; n++) {
        double mm  = (double)n - 250.0;
        double fc  = 1.0 / 25.0;
        double xx  = fc * mm;
        double snc = (n == 250) ? 1.0 : (c_sin(PI_D * xx) / (PI_D * xx));
        double r   = mm / 250.0;
        double arg = 1.0 - r * r;
        double w   = c_i0(5.0 * c_sqrt(arg < 0.0 ? 0.0 : arg)) / i0b;
        ht[n] = fc * snc * w;
    }
    double s = 0.0;
    for (int n = 0; n < 501; n++) s += ht[n];
    Fir F{};
    for (int i = 0; i < 25; i++) F.h[i] = 0.0f;
    for (int n = 0; n < 501; n++) F.h[25 + n] = (float)(ht[n] / s * 16.0);
    return F;
}
__device__ const Fir g_fir = make_fir();

struct CoefD { double b[3][3]; double a[3][2]; double zi[3][2]; };
constexpr CoefD make_coefd() {
    double warped = 4.0 * c_tan(PI_D * 0.01 / 2.0);
    double pr[6] = {}, pim[6] = {};
    for (int i = 0; i < 6; i++) {
        int m = -5 + 2 * i;
        double th = PI_D * (double)m / 12.0;
        double ar = -c_cos(th), ai = -c_sin(th);
        double den = ar * ar + ai * ai;
        pr[i]  =  warped * ar / den;
        pim[i] = -warped * ai / den;
    }
    double qr = 1.0, qi = 0.0;
    for (int i = 0; i < 6; i++) {
        double xr = 4.0 - pr[i], xi = -pim[i];
        double nr = qr * xr - qi * xi;
        double ni = qr * xi + qi * xr;
        qr = nr; qi = ni;
    }
    double kk = 4096.0 * qr / (qr * qr + qi * qi);
    double dr[6] = {}, di[6] = {};
    for (int i = 0; i < 6; i++) {
        double nr = 4.0 + pr[i], ni = pim[i];
        double mr = 4.0 - pr[i], mi = -pim[i];
        double dd = mr * mr + mi * mi;
        dr[i] = (nr * mr + ni * mi) / dd;
        di[i] = (ni * mr - nr * mi) / dd;
    }
    double sr[3] = {}, si[3] = {}; int c = 0;
    for (int i = 0; i < 6; i++) if (di[i] > 0.0) { sr[c] = dr[i]; si[c] = di[i]; c++; }
    double key[3] = {};
    for (int i = 0; i < 3; i++) {
        double mag = c_sqrt(sr[i] * sr[i] + si[i] * si[i]);
        double dv = mag - 1.0;
        key[i] = dv < 0.0 ? -dv : dv;
    }
    int ord[3] = {0, 1, 2};
    for (int a = 0; a < 3; a++)
        for (int b = a + 1; b < 3; b++)
            if (key[ord[b]] > key[ord[a]]) { int t = ord[a]; ord[a] = ord[b]; ord[b] = t; }
    CoefD C{};
    double zs = 1.0;
    for (int s2 = 0; s2 < 3; s2++) {
        int i = ord[s2];
        double b0 = (s2 == 0) ? kk : 1.0;
        double b1 = -2.0 * b0, b2 = b0;
        double a1 = -2.0 * sr[i];
        double a2 = sr[i] * sr[i] + si[i] * si[i];
        C.b[s2][0] = b0; C.b[s2][1] = b1; C.b[s2][2] = b2;
        C.a[s2][0] = a1; C.a[s2][1] = a2;
        double det = 1.0 + a1 + a2;
        double B0 = b1 - a1 * b0, B1 = b2 - a2 * b0;
        double z0 = (B0 + B1) / det;
        double z1 = (-a2 * B0 + (1.0 + a1) * B1) / det;
        C.zi[s2][0] = zs * z0;
        C.zi[s2][1] = zs * z1;
        zs *= (b0 + b1 + b2) / det;
    }
    return C;
}
constexpr CoefD KD = make_coefd();

constexpr float KB00=(float)KD.b[0][0], KB01=(float)KD.b[0][1], KB02=(float)KD.b[0][2];
constexpr float KB10=(float)KD.b[1][0], KB11=(float)KD.b[1][1], KB12=(float)KD.b[1][2];
constexpr float KB20=(float)KD.b[2][0], KB21=(float)KD.b[2][1], KB22=(float)KD.b[2][2];
constexpr float KA01=(float)KD.a[0][0], KA02=(float)KD.a[0][1];
constexpr float KA11=(float)KD.a[1][0], KA12=(float)KD.a[1][1];
constexpr float KA21=(float)KD.a[2][0], KA22=(float)KD.a[2][1];
constexpr float KZ00=(float)KD.zi[0][0], KZ01=(float)KD.zi[0][1];
constexpr float KZ10=(float)KD.zi[1][0], KZ11=(float)KD.zi[1][1];
constexpr float KZ20=(float)KD.zi[2][0], KZ21=(float)KD.zi[2][1];

struct StepR { double s[6]; double y; };
constexpr StepR ss_step(const double* s, double v) {
    double y0  = KD.b[0][0]*v + s[0];
    double z00 = KD.b[0][1]*v - KD.a[0][0]*y0 + s[1];
    double z01 = KD.b[0][2]*v - KD.a[0][1]*y0;
    double y1  = KD.b[1][0]*y0 + s[2];
    double z10 = KD.b[1][1]*y0 - KD.a[1][0]*y1 + s[3];
    double z11 = KD.b[1][2]*y0 - KD.a[1][1]*y1;
    double y2  = KD.b[2][0]*y1 + s[4];
    double z20 = KD.b[2][1]*y1 - KD.a[2][0]*y2 + s[5];
    double z21 = KD.b[2][2]*y1 - KD.a[2][1]*y2;
    return StepR{{z00,z01,z10,z11,z20,z21}, y2};
}
struct Tables { float ACL[6][6]; };
constexpr Tables make_tables() {
    double P[6][6] = {};
    for (int j = 0; j < 6; j++) {
        double e[6] = {}; e[j] = 1.0;
        StepR r = ss_step(e, 0.0);
        for (int i = 0; i < 6; i++) P[i][j] = r.s[i];
    }
    for (int k = 0; k < CLLOG; k++) {      // A -> A^CL
        double Q[6][6] = {};
        for (int i = 0; i < 6; i++)
            for (int l = 0; l < 6; l++) {
                double acc = 0.0;
                for (int j = 0; j < 6; j++) acc += P[i][j] * P[j][l];
                Q[i][l] = acc;
            }
        for (int i = 0; i < 6; i++) for (int l = 0; l < 6; l++) P[i][l] = Q[i][l];
    }
    Tables T{};
    for (int i = 0; i < 6; i++) for (int j = 0; j < 6; j++) T.ACL[i][j] = (float)P[i][j];
    return T;
}
constexpr Tables TB = make_tables();
#define TBA(i,j) (TB.ACL[i][j])

// ---------------- small asm helpers ----------------
__device__ __forceinline__ u32 hpack(float lo, float hi) {
    u32 d; asm("cvt.rn.f16x2.f32 %0, %1, %2;" : "=r"(d) : "f"(hi), "f"(lo)); return d;
}
__device__ __forceinline__ u32 ex2h2(u32 x) {
    u32 y; asm("ex2.approx.f16x2 %0, %1;" : "=r"(y) : "r"(x)); return y;
}

#define MMA_F16(c, a, b0_, b1_)                                                         \
    asm("mma.sync.aligned.m16n8k16.row.col.f32.f16.f16.f32 "                            \
        "{%0,%1,%2,%3},{%4,%5,%6,%7},{%8,%9},{%0,%1,%2,%3};"                            \
        : "+f"((c)[0]), "+f"((c)[1]), "+f"((c)[2]), "+f"((c)[3])                        \
        : "r"((a)[0]), "r"((a)[1]), "r"((a)[2]), "r"((a)[3]), "r"(b0_), "r"(b1_))

// ---------------- init: PE table + pool zero ----------------
__global__ void eeg_init_pe_kernel() {
    int e = blockIdx.x * blockDim.x + threadIdx.x;
    if (e < TR * DM) {
        int pos = e / DM, d = e % DM;
        double div = exp(-((double)(d & ~1)) * log(10000.0) / 16.0);
        double ang = (double)pos * div;
        g_pe[e] = (float)((d & 1) ? cos(ang) : sin(ang));
    }
    if (e < BB * DM) g_pool[e] = 0.f;
}

// ---------------- stage 1: mean over selected channels ----------------
__global__ void eeg_mean_kernel(const float* __restrict__ x) {
    int idx = blockIdx.x * blockDim.x + threadIdx.x;
    if (idx >= BB * TT) return;
    int b = idx / TT, t = idx % TT;
    float s = 0.f;
    #pragma unroll
    for (int c = 0; c < 10; c++) s += x[((long)(b * 128 + d_CH[c])) * TT + t];
    g_mean[idx] = s * (1.0f / 10.0f);
}

// ---------------- stage 1b: build extended, padded, TRANSPOSED signal ----------------
__global__ void eeg_buildext_kernel(const float* __restrict__ x) {
    int idx = blockIdx.x * blockDim.x + threadIdx.x;
    if (idx >= TE * NROWS) return;
    int t = idx / NROWS, row = idx % NROWS;
    int b = row / NCHS, c = row % NCHS;
    const float* xp = x + ((long)(b * 128 + d_CH[c])) * TT;
    const float* mp = g_mean + (long)b * TT;
    float v;
    if (t < PADL) {
        float c0 = xp[0] - mp[0];
        int j = PADL - t;
        v = 2.f * c0 - (xp[j] - mp[j]);
    } else if (t < PADL + TT) {
        int j = t - PADL;
        v = xp[j] - mp[j];
    } else {
        float cl = xp[TT - 1] - mp[TT - 1];
        int j = 1998 - (t - (PADL + TT));
        v = 2.f * cl - (xp[j] - mp[j]);
    }
    g_extT[idx] = v;
}

// ---------------- biquad step (immediate coefficients) ----------------
#define BQ_IMM(v, y2out)                                   \
    {                                                      \
        float y0 = fmaf(KB00, (v), z00);                   \
        z00 = fmaf(-KA01, y0, fmaf(KB01, (v), z01));       \
        z01 = fmaf(-KA02, y0, KB02 * (v));                 \
        float y1 = fmaf(KB10, y0, z10);                    \
        z10 = fmaf(-KA11, y1, fmaf(KB11, y0, z11));        \
        z11 = fmaf(-KA12, y1, KB12 * y0);                  \
        y2out = fmaf(KB20, y1, z20);                       \
        z20 = fmaf(-KA21, y2out, fmaf(KB21, y1, z21));     \
        z21 = fmaf(-KA22, y2out, KB22 * y1);               \
    }

#define BQH_IMM(y2out)                                     \
    {                                                      \
        float y0 = z00;                                    \
        z00 = fmaf(-KA01, y0, z01);                        \
        z01 = -KA02 * y0;                                  \
        float y1 = fmaf(KB10, y0, z10);                    \
        z10 = fmaf(-KA11, y1, fmaf(KB11, y0, z11));        \
        z11 = fmaf(-KA12, y1, KB12 * y0);                  \
        y2out = fmaf(KB20, y1, z20);                       \
        z20 = fmaf(-KA21, y2out, fmaf(KB21, y1, z21));     \
        z21 = fmaf(-KA22, y2out, KB22 * y1);               \
    }

// ---------------- stage 2a: fwd phase A ----------------
__global__ void __launch_bounds__(32, 1) eeg_fA_kernel() {
    int row = blockIdx.x * 32 + threadIdx.x;
    int c = blockIdx.y;
    int base = c * CL;
    int Lc = (c == CH - 1) ? (TE - (CH - 1) * CL) : CL;
    float z00, z01, z10, z11, z20, z21;
    if (c == 0) {
        float x0 = g_extT[row];
        z00 = KZ00 * x0; z01 = KZ01 * x0;
        z10 = KZ10 * x0; z11 = KZ11 * x0;
        z20 = KZ20 * x0; z21 = KZ21 * x0;
    } else {
        z00 = z01 = z10 = z11 = z20 = z21 = 0.f;
    }
    const float* src = g_extT + row;
    float* dst = g_wrkT + row;
    float bufA[PF], bufB[PF];
    #pragma unroll
    for (int i = 0; i < PF; i++) bufA[i] = src[(base + i) * NROWS];
    int nblk = Lc / PF;
    int t0 = base;
    for (int blk = 0; blk < nblk; blk++, t0 += PF) {
        #pragma unroll
        for (int i = 0; i < PF; i++) bufB[i] = src[(t0 + PF + i) * NROWS];
        #pragma unroll
        for (int i = 0; i < PF; i++) { float y2; BQ_IMM(bufA[i], y2); dst[(t0 + i) * NROWS] = y2; }
        #pragma unroll
        for (int i = 0; i < PF; i++) bufA[i] = bufB[i];
    }
    for (int i = 0; i < Lc - nblk * PF; i++) { float y2; BQ_IMM(bufA[i], y2); dst[(t0 + i) * NROWS] = y2; }
    if (c < CH - 1) {
        g_es[c][0][row] = z00; g_es[c][1][row] = z01; g_es[c][2][row] = z10;
        g_es[c][3][row] = z11; g_es[c][4][row] = z20; g_es[c][5][row] = z21;
    }
}

// ---------------- state propagation helper ----------------
#define PROPAGATE(ES)                                                                            \
    float s0 = ES[0][0][row], s1 = ES[0][1][row], s2 = ES[0][2][row];                            \
    float s3 = ES[0][3][row], s4 = ES[0][4][row], s5 = ES[0][5][row];                            \
    for (int i = 1; i < c; i++) {                                                                \
        float e0 = ES[i][0][row], e1 = ES[i][1][row], e2 = ES[i][2][row];                        \
        float e3 = ES[i][3][row], e4 = ES[i][4][row], e5 = ES[i][5][row];                        \
        float n0 = fmaf(TBA(0,0),s0, fmaf(TBA(0,1),s1, fmaf(TBA(0,2),s2, fmaf(TBA(0,3),s3, fmaf(TBA(0,4),s4, fmaf(TBA(0,5),s5, e0)))))); \
        float n1 = fmaf(TBA(1,0),s0, fmaf(TBA(1,1),s1, fmaf(TBA(1,2),s2, fmaf(TBA(1,3),s3, fmaf(TBA(1,4),s4, fmaf(TBA(1,5),s5, e1)))))); \
        float n2 = fmaf(TBA(2,0),s0, fmaf(TBA(2,1),s1, fmaf(TBA(2,2),s2, fmaf(TBA(2,3),s3, fmaf(TBA(2,4),s4, fmaf(TBA(2,5),s5, e2)))))); \
        float n3 = fmaf(TBA(3,0),s0, fmaf(TBA(3,1),s1, fmaf(TBA(3,2),s2, fmaf(TBA(3,3),s3, fmaf(TBA(3,4),s4, fmaf(TBA(3,5),s5, e3)))))); \
        float n4 = fmaf(TBA(4,0),s0, fmaf(TBA(4,1),s1, fmaf(TBA(4,2),s2, fmaf(TBA(4,3),s3, fmaf(TBA(4,4),s4, fmaf(TBA(4,5),s5, e4)))))); \
        float n5 = fmaf(TBA(5,0),s0, fmaf(TBA(5,1),s1, fmaf(TBA(5,2),s2, fmaf(TBA(5,3),s3, fmaf(TBA(5,4),s4, fmaf(TBA(5,5),s5, e5)))))); \
        s0 = n0; s1 = n1; s2 = n2; s3 = n3; s4 = n4; s5 = n5;                                    \
    }

// ---------------- stage 2b: fwd phase C ----------------
__global__ void __launch_bounds__(32, 1) eeg_fC_kernel() {
    int row = blockIdx.x * 32 + threadIdx.x;
    int c = blockIdx.y + 1;
    PROPAGATE(g_es);
    float z00 = s0, z01 = s1, z10 = s2, z11 = s3, z20 = s4, z21 = s5;
    int base = c * CL;
    int Lc = (c == CH - 1) ? (TE - (CH - 1) * CL) : CL;
    float* p = g_wrkT + row;
    float bufA[PF], bufB[PF];
    #pragma unroll
    for (int i = 0; i < PF; i++) bufA[i] = p[(base + i) * NROWS];
    int nblk = Lc / PF;
    int t0 = base;
    for (int blk = 0; blk < nblk; blk++, t0 += PF) {
        #pragma unroll
        for (int i = 0; i < PF; i++) bufB[i] = p[(t0 + PF + i) * NROWS];
        #pragma unroll
        for (int i = 0; i < PF; i++) { float yh; BQH_IMM(yh); p[(t0 + i) * NROWS] = bufA[i] + yh; }
        #pragma unroll
        for (int i = 0; i < PF; i++) bufA[i] = bufB[i];
    }
    for (int i = 0; i < Lc - nblk * PF; i++) { float yh; BQH_IMM(yh); p[(t0 + i) * NROWS] = bufA[i] + yh; }
}

// ---------------- stage 2c: bwd phase A ----------------
__global__ void __launch_bounds__(32, 1) eeg_bA_kernel() {
    int row = blockIdx.x * 32 + threadIdx.x;
    int c = blockIdx.y;
    int base = c * CL;
    int Lc = (c == CH - 1) ? (TE - (CH - 1) * CL) : CL;
    float z00, z01, z10, z11, z20, z21;
    if (c == 0) {
        float x0 = g_wrkT[(TE - 1) * NROWS + row];
        z00 = KZ00 * x0; z01 = KZ01 * x0;
        z10 = KZ10 * x0; z11 = KZ11 * x0;
        z20 = KZ20 * x0; z21 = KZ21 * x0;
    } else {
        z00 = z01 = z10 = z11 = z20 = z21 = 0.f;
    }
    const float* src = g_wrkT + row;
    float* yrow = g_yf + (long)row * TT;
    float bufA[PF], bufB[PF];
    #pragma unroll
    for (int i = 0; i < PF; i++) {
        int s = TE - 1 - (base + i);
        bufA[i] = src[((s > 0) ? s : 0) * NROWS];
    }
    int nblk = Lc / PF;
    int t0 = base;
    for (int blk = 0; blk < nblk; blk++, t0 += PF) {
        #pragma unroll
        for (int i = 0; i < PF; i++) {
            int s = TE - 1 - (t0 + PF + i);
            bufB[i] = src[((s > 0) ? s : 0) * NROWS];
        }
        #pragma unroll
        for (int i = 0; i < PF; i++) {
            float y2; BQ_IMM(bufA[i], y2);
            int rt = t0 + i;
            if (c == 0) {
                int tau = 2020 - rt;
                if (tau < TT) yrow[tau] = y2;
            } else {
                g_extT[rt * NROWS + row] = y2;
            }
        }
        #pragma unroll
        for (int i = 0; i < PF; i++) bufA[i] = bufB[i];
    }
    for (int i = 0; i < Lc - nblk * PF; i++) {
        float y2; BQ_IMM(bufA[i], y2);
        int rt = t0 + i;
        if (c == 0) {
            int tau = 2020 - rt;
            if (tau < TT) yrow[tau] = y2;
        } else {
            g_extT[rt * NROWS + row] = y2;
        }
    }
    if (c < CH - 1) {
        g_esb[c][0][row] = z00; g_esb[c][1][row] = z01; g_esb[c][2][row] = z10;
        g_esb[c][3][row] = z11; g_esb[c][4][row] = z20; g_esb[c][5][row] = z21;
    }
}

// ---------------- stage 2d: bwd phase C ----------------
__global__ void __launch_bounds__(32, 1) eeg_bC_kernel() {
    int row = blockIdx.x * 32 + threadIdx.x;
    int c = blockIdx.y + 1;
    PROPAGATE(g_esb);
    float z00 = s0, z01 = s1, z10 = s2, z11 = s3, z20 = s4, z21 = s5;
    int base = c * CL;
    int Lc = (c == CH - 1) ? (TE - (CH - 1) * CL) : CL;
    const float* p = g_extT + row;
    float* yrow = g_yf + (long)row * TT;
    float bufA[PF], bufB[PF];
    #pragma unroll
    for (int i = 0; i < PF; i++) bufA[i] = p[(base + i) * NROWS];
    int nblk = Lc / PF;
    int t0 = base;
    for (int blk = 0; blk < nblk; blk++, t0 += PF) {
        #pragma unroll
        for (int i = 0; i < PF; i++) bufB[i] = p[(t0 + PF + i) * NROWS];
        #pragma unroll
        for (int i = 0; i < PF; i++) {
            float yh; BQH_IMM(yh);
            int tau = 2020 - (t0 + i);
            if (tau >= 0) yrow[tau] = bufA[i] + yh;
        }
        #pragma unroll
        for (int i = 0; i < PF; i++) bufA[i] = bufB[i];
    }
    for (int i = 0; i < Lc - nblk * PF; i++) {
        float yh; BQH_IMM(yh);
        int tau = 2020 - (t0 + i);
        if (tau >= 0) yrow[tau] = bufA[i] + yh;
    }
}

// ---------------- stage 3: polyphase resample + tanh + per-row standardize ----------------
__global__ void eeg_resample_kernel() {
    __shared__ float yf[TT];
    __shared__ float tv[TR];
    __shared__ float hh[526];
    __shared__ float red[256];
    int row = blockIdx.x, tid = threadIdx.x;
    const float* src = g_yf + (long)row * TT;
    for (int t = tid; t < TT; t += 256) yf[t] = src[t];
    for (int i = tid; i < 526; i += 256) hh[i] = g_fir.h[i];
    __syncthreads();
    for (int n = tid; n < TR; n += 256) {
        int A = (n + 11) * 25;
        int tlo = A - 525 + 15;
        tlo = (tlo > 0) ? (tlo >> 4) : 0;
        int thi = A >> 4;
        if (thi > TT - 1) thi = TT - 1;
        float s0 = 0.f, s1 = 0.f, s2 = 0.f, s3 = 0.f;
        int t = tlo, idx = A - 16 * tlo;
        for (; t + 3 <= thi; t += 4, idx -= 64) {
            s0 = fmaf(yf[t],     hh[idx],      s0);
            s1 = fmaf(yf[t + 1], hh[idx - 16], s1);
            s2 = fmaf(yf[t + 2], hh[idx - 32], s2);
            s3 = fmaf(yf[t + 3], hh[idx - 48], s3);
        }
        for (; t <= thi; t++, idx -= 16) s0 = fmaf(yf[t], hh[idx], s0);
        tv[n] = tanhf((s0 + s1) + (s2 + s3));
    }
    __syncthreads();
    float ls = 0.f;
    for (int n = tid; n < TR; n += 256) ls += tv[n];
    red[tid] = ls; __syncthreads();
    for (int st = 128; st > 0; st >>= 1) { if (tid < st) red[tid] += red[tid + st]; __syncthreads(); }
    float mean = red[0] * (1.f / TR);
    __syncthreads();
    float lv = 0.f;
    for (int n = tid; n < TR; n += 256) { float d = tv[n] - mean; lv = fmaf(d, d, lv); }
    red[tid] = lv; __syncthreads();
    for (int st = 128; st > 0; st >>= 1) { if (tid < st) red[tid] += red[tid + st]; __syncthreads(); }
    float var  = red[0] * (1.f / (TR - 1));
    float stdv = fmaxf(sqrtf(var), 1e-6f);
    float inv  = 1.f / stdv;
    float* dst = g_xr + (long)row * TR;
    for (int n = tid; n < TR; n += 256) dst[n] = (tv[n] - mean) * inv;
}

// ---------------- stage 4+5 fused: conv1d + relu + LN0 + PE + QKV ----------------
__global__ void eeg_convqkv_kernel(const float* __restrict__ cw, const float* __restrict__ cb,
                                   const float* __restrict__ ln0g, const float* __restrict__ ln0b,
                                   const float* __restrict__ wqkv, const float* __restrict__ bqkv) {
    __shared__ float w[480];
    __shared__ float bias[16], sg[16], sb[16];
    __shared__ float wq[768];
    __shared__ float bq[48];
    int tid = threadIdx.x;
    for (int i = tid; i < 480; i += blockDim.x) w[i] = cw[i];
    for (int i = tid; i < 768; i += blockDim.x) wq[i] = wqkv[i];
    if (tid < 16) { bias[tid] = cb[tid]; sg[tid] = ln0g[tid]; sb[tid] = ln0b[tid]; }
    if (tid < 48) bq[tid] = bqkv[tid];
    __syncthreads();
    int idx = blockIdx.x * blockDim.x + tid;   // b*TR + n
    if (idx >= BB * TR) return;
    int b = idx / TR, n = idx % TR;
    float xin[10][3];
    #pragma unroll
    for (int i = 0; i < 10; i++) {
        const float* base = g_xr + ((long)b * NCHS + i) * TR + n;
        xin[i][0] = (n > 0)      ? base[-1] : 0.f;
        xin[i][1] = base[0];
        xin[i][2] = (n < TR - 1) ? base[1]  : 0.f;
    }
    float o[16];
    #pragma unroll
    for (int oc = 0; oc < 16; oc++) {
        float s = bias[oc];
        #pragma unroll
        for (int i = 0; i < 10; i++) {
            s = fmaf(w[oc * 30 + i * 3 + 0], xin[i][0], s);
            s = fmaf(w[oc * 30 + i * 3 + 1], xin[i][1], s);
            s = fmaf(w[oc * 30 + i * 3 + 2], xin[i][2], s);
        }
        o[oc] = fmaxf(s, 0.f);
    }
    float mu = 0.f;
    #pragma unroll
    for (int d = 0; d < 16; d++) mu += o[d];
    mu *= (1.f / 16);
    float var = 0.f;
    #pragma unroll
    for (int d = 0; d < 16; d++) { float dd = o[d] - mu; var = fmaf(dd, dd, var); }
    var *= (1.f / 16);
    float r = rsqrtf(var + 1e-5f);
    float xv[16];
    const float* pe = g_pe + n * 16;
    float* dst = g_h0 + (long)idx * 16;
    #pragma unroll
    for (int d = 0; d < 16; d++) {
        xv[d] = fmaf((o[d] - mu) * r, sg[d], sb[d]) + pe[d];
        dst[d] = xv[d];
    }
    float* qd = g_q + (long)idx * 16;
    float* kd = g_k + (long)idx * 16;
    float* vd = g_v + (long)idx * 16;
    const float QSCALE = 0.25f * 1.4426950408889634f;
    #pragma unroll
    for (int j = 0; j < 16; j++) {
        float sq = bq[j], sk = bq[16 + j], sv = bq[32 + j];
        #pragma unroll
        for (int d = 0; d < 16; d++) {
            sq = fmaf(wq[j * 16 + d],        xv[d], sq);
            sk = fmaf(wq[(16 + j) * 16 + d], xv[d], sk);
            sv = fmaf(wq[(32 + j) * 16 + d], xv[d], sv);
        }
        qd[j] = sq * QSCALE;
        kd[j] = sk;
        vd[j] = sv;
    }
}

// ---------------- LN helper ----------------
__device__ __forceinline__ void ln16(float* v, const float* g, const float* b) {
    float mu = 0.f;
    #pragma unroll
    for (int d = 0; d < 16; d++) mu += v[d];
    mu *= (1.f / 16);
    float var = 0.f;
    #pragma unroll
    for (int d = 0; d < 16; d++) { float dd = v[d] - mu; var = fmaf(dd, dd, var); }
    var *= (1.f / 16);
    float r = rsqrtf(var + 1e-5f);
    #pragma unroll
    for (int d = 0; d < 16; d++) v[d] = fmaf((v[d] - mu) * r, g[d], b[d]);
}

// =====================================================================
// stage 6: tensor-core flash attention (fp16 QK + fp16 PV, ex2.f16x2)
// block = 128 threads = 4 warps; warp w owns query rows 32w..32w+31
// =====================================================================
__global__ void __launch_bounds__(128) eeg_attn_kernel(
                                const float* __restrict__ wo, const float* __restrict__ bo,
                                const float* __restrict__ w1, const float* __restrict__ b1,
                                const float* __restrict__ w2, const float* __restrict__ b2,
                                const float* __restrict__ l1g, const float* __restrict__ l1b,
                                const float* __restrict__ l2g, const float* __restrict__ l2b) {
    __shared__ float smemA[2176];       // KTH fp16 tile (8 x 132 u32) / later ovs (128 x 17)
    __shared__ u32   vp[64 * 24];       // V f16x2 pairs: [pair][dim24] (dim16 = ones)
    __shared__ float swo[256], sbo[16], sw1[512], sb1[32], sw2[512], sb2[16];
    __shared__ float sl1g[16], sl1b[16], sl2g[16], sl2b[16];
    u32* KTH = (u32*)smemA;             // [dimpair 0..7][key 0..127], stride 132
    int tid = threadIdx.x;
    int lane = tid & 31, w = tid >> 5;
    int g = lane >> 2, qd4 = lane & 3;

    for (int i = tid; i < 256; i += 128) swo[i] = wo[i];
    for (int i = tid; i < 512; i += 128) { sw1[i] = w1[i]; sw2[i] = w2[i]; }
    if (tid < 16) {
        sbo[tid] = bo[tid]; sb2[tid] = b2[tid];
        sl1g[tid] = l1g[tid]; sl1b[tid] = l1b[tid];
        sl2g[tid] = l2g[tid]; sl2b[tid] = l2b[tid];
    }
    if (tid < 32) sb1[tid] = b1[tid];

    int b = blockIdx.x / 10, qt = blockIdx.x % 10;
    long bTR = (long)b * TR;
    int qrow0 = qt * 128;

    // ---- Q A-fragments (m16n8k16 fp16 layout), loaded once ----
    u32 qh[2][4];
    #pragma unroll
    for (int m = 0; m < 2; m++) {
        const float* qp = g_q + (bTR + qrow0 + 32 * w + 16 * m + g) * 16;
        qh[m][0] = hpack(qp[2 * qd4],           qp[2 * qd4 + 1]);
        qh[m][1] = hpack(qp[128 + 2 * qd4],     qp[128 + 2 * qd4 + 1]);   // row+8
        qh[m][2] = hpack(qp[2 * qd4 + 8],       qp[2 * qd4 + 9]);
        qh[m][3] = hpack(qp[128 + 2 * qd4 + 8], qp[128 + 2 * qd4 + 9]);
    }

    // ---- O accumulators: 2 m-tiles x 3 n8 dim-tiles (dims 0-7, 8-15, 16-23) ----
    float oc[2][3][4];
    #pragma unroll
    for (int m = 0; m < 2; m++)
        #pragma unroll
        for (int dt = 0; dt < 3; dt++)
            #pragma unroll
            for (int e = 0; e < 4; e++) oc[m][dt][e] = 0.f;

    for (int kb = 0; kb < 10; kb++) {
        __syncthreads();
        // stage K as fp16 pairs [dimpair][key] (stride 132)
        {
            const float4* kp = (const float4*)(g_k + (bTR + kb * 128 + tid) * 16);
            float4 r0 = kp[0], r1 = kp[1], r2 = kp[2], r3 = kp[3];
            KTH[0 * 132 + tid] = hpack(r0.x, r0.y);
            KTH[1 * 132 + tid] = hpack(r0.z, r0.w);
            KTH[2 * 132 + tid] = hpack(r1.x, r1.y);
            KTH[3 * 132 + tid] = hpack(r1.z, r1.w);
            KTH[4 * 132 + tid] = hpack(r2.x, r2.y);
            KTH[5 * 132 + tid] = hpack(r2.z, r2.w);
            KTH[6 * 132 + tid] = hpack(r3.x, r3.y);
            KTH[7 * 132 + tid] = hpack(r3.z, r3.w);
        }
        // stage V as f16x2 key-pairs [pair][dim], + ones/zero columns
        if (tid < 64) {
            const float4* v0 = (const float4*)(g_v + (bTR + kb * 128 + 2 * tid) * 16);
            float4 a0 = v0[0], a1 = v0[1], a2 = v0[2], a3 = v0[3];
            float4 b0_ = v0[4], b1_ = v0[5], b2_ = v0[6], b3_ = v0[7];
            u32* vd = vp + tid * 24;
            vd[0]  = hpack(a0.x, b0_.x); vd[1]  = hpack(a0.y, b0_.y);
            vd[2]  = hpack(a0.z, b0_.z); vd[3]  = hpack(a0.w, b0_.w);
            vd[4]  = hpack(a1.x, b1_.x); vd[5]  = hpack(a1.y, b1_.y);
            vd[6]  = hpack(a1.z, b1_.z); vd[7]  = hpack(a1.w, b1_.w);
            vd[8]  = hpack(a2.x, b2_.x); vd[9]  = hpack(a2.y, b2_.y);
            vd[10] = hpack(a2.z, b2_.z); vd[11] = hpack(a2.w, b2_.w);
            vd[12] = hpack(a3.x, b3_.x); vd[13] = hpack(a3.y, b3_.y);
            vd[14] = hpack(a3.z, b3_.z); vd[15] = hpack(a3.w, b3_.w);
        } else {
            u32* vd = vp + (tid - 64) * 24;
            vd[16] = 0x3C003C00u;   // ones column (fp16 1.0, 1.0)
            #pragma unroll
            for (int d = 17; d < 24; d++) vd[d] = 0u;
        }
        __syncthreads();

        #pragma unroll 1
        for (int np = 0; np < 8; np++) {
            // ---- S fragments for 16 keys (two n8 blocks), fp16 k16 MMA ----
            float sc[2][2][4];
            #pragma unroll
            for (int m = 0; m < 2; m++)
                #pragma unroll
                for (int nb = 0; nb < 2; nb++)
                    #pragma unroll
                    for (int e = 0; e < 4; e++) sc[m][nb][e] = 0.f;
            #pragma unroll
            for (int nb = 0; nb < 2; nb++) {
                int key0 = 16 * np + 8 * nb + g;
                u32 kb0 = KTH[qd4 * 132 + key0];
                u32 kb1 = KTH[(qd4 + 4) * 132 + key0];
                #pragma unroll
                for (int m = 0; m < 2; m++) MMA_F16(sc[m][nb], qh[m], kb0, kb1);
            }
            // ---- p = 2^s in packed fp16, direct A-frags ----
            u32 pa[2][4];
            #pragma unroll
            for (int m = 0; m < 2; m++) {
                pa[m][0] = ex2h2(hpack(sc[m][0][0], sc[m][0][1]));
                pa[m][1] = ex2h2(hpack(sc[m][0][2], sc[m][0][3]));
                pa[m][2] = ex2h2(hpack(sc[m][1][0], sc[m][1][1]));
                pa[m][3] = ex2h2(hpack(sc[m][1][2], sc[m][1][3]));
            }
            // ---- PV: 3 dim-tiles (incl. ones column for l) ----
            #pragma unroll
            for (int dt = 0; dt < 3; dt++) {
                u32 vb0 = vp[(8 * np + qd4) * 24 + dt * 8 + g];
                u32 vb1 = vp[(8 * np + 4 + qd4) * 24 + dt * 8 + g];
                #pragma unroll
                for (int m = 0; m < 2; m++) MMA_F16(oc[m][dt], pa[m], vb0, vb1);
            }
        }
    }
    __syncthreads();   // done with KTH; reuse as ovs

    // ---- normalize by l (ones column, col 16 -> lane%4==0) and write ovs ----
    float* ovs = smemA;
    #pragma unroll
    for (int m = 0; m < 2; m++) {
        float l0 = __shfl_sync(0xffffffffu, oc[m][2][0], lane & ~3);
        float l1 = __shfl_sync(0xffffffffu, oc[m][2][2], lane & ~3);
        float i0 = 1.f / l0, i1 = 1.f / l1;
        int r0 = 32 * w + 16 * m + g, r1 = r0 + 8;
        #pragma unroll
        for (int dt = 0; dt < 2; dt++) {
            int col = dt * 8 + 2 * qd4;
            ovs[r0 * 17 + col]     = oc[m][dt][0] * i0;
            ovs[r0 * 17 + col + 1] = oc[m][dt][1] * i0;
            ovs[r1 * 17 + col]     = oc[m][dt][2] * i1;
            ovs[r1 * 17 + col + 1] = oc[m][dt][3] * i1;
        }
    }
    __syncthreads();

    // ---- epilogue per query (tid) ----
    float ov[16];
    #pragma unroll
    for (int d = 0; d < 16; d++) ov[d] = ovs[tid * 17 + d];
    float h0v[16];
    {
        const float4* hs = (const float4*)(g_h0 + (bTR + qrow0 + tid) * 16);
        float4 a0 = hs[0], a1 = hs[1], a2 = hs[2], a3 = hs[3];
        h0v[0] = a0.x; h0v[1] = a0.y; h0v[2] = a0.z; h0v[3] = a0.w;
        h0v[4] = a1.x; h0v[5] = a1.y; h0v[6] = a1.z; h0v[7] = a1.w;
        h0v[8] = a2.x; h0v[9] = a2.y; h0v[10] = a2.z; h0v[11] = a2.w;
        h0v[12] = a3.x; h0v[13] = a3.y; h0v[14] = a3.z; h0v[15] = a3.w;
    }
    float x1[16];
    #pragma unroll
    for (int d = 0; d < 16; d++) {
        float s = sbo[d];
        #pragma unroll
        for (int e = 0; e < 16; e++) s = fmaf(swo[d * 16 + e], ov[e], s);
        x1[d] = h0v[d] + s;
    }
    ln16(x1, sl1g, sl1b);
    float f[16];
    #pragma unroll
    for (int d = 0; d < 16; d++) f[d] = sb2[d];
    #pragma unroll
    for (int j = 0; j < 32; j++) {
        float t = sb1[j];
        #pragma unroll
        for (int e = 0; e < 16; e++) t = fmaf(sw1[j * 16 + e], x1[e], t);
        t = fmaxf(t, 0.f);
        #pragma unroll
        for (int d = 0; d < 16; d++) f[d] = fmaf(sw2[d * 32 + j], t, f[d]);
    }
    float x2[16];
    #pragma unroll
    for (int d = 0; d < 16; d++) x2[d] = x1[d] + f[d];
    ln16(x2, sl2g, sl2b);
    __syncthreads();
    float* R = smemA;
    #pragma unroll
    for (int d = 0; d < 16; d++) R[tid * 16 + d] = x2[d];
    __syncthreads();
    for (int st = 64; st > 0; st >>= 1) {
        if (tid < st) {
            #pragma unroll
            for (int d = 0; d < 16; d++) R[tid * 16 + d] += R[(tid + st) * 16 + d];
        }
        __syncthreads();
    }
    if (tid < 16) atomicAdd(&g_pool[b * 16 + tid], R[tid]);
}

// ---------------- stage 7: head ----------------
__global__ void eeg_head_kernel(const float* __restrict__ wfc, const float* __restrict__ bfc,
                                float* __restrict__ out) {
    int b = threadIdx.x;
    if (b < BB) {
        float s = 0.f;
        #pragma unroll
        for (int d = 0; d < 16; d++) s = fmaf(g_pool[b * 16 + d], wfc[d], s);
        out[b] = s * (1.f / (float)TR) + bfc[0];
    }
}

// ---------------- launch ----------------
extern "C" void kernel_launch(void* const* d_in, const int* in_sizes, int n_in,
                              void* d_out, int out_size) {
    const float* x      = (const float*)d_in[0];
    const float* conv_w = (const float*)d_in[1];
    const float* conv_b = (const float*)d_in[2];
    const float* ln0g   = (const float*)d_in[3];
    const float* ln0b   = (const float*)d_in[4];
    const float* wqkv   = (const float*)d_in[5];
    const float* bqkv   = (const float*)d_in[6];
    const float* wo     = (const float*)d_in[7];
    const float* bo     = (const float*)d_in[8];
    const float* w1     = (const float*)d_in[9];
    const float* b1     = (const float*)d_in[10];
    const float* w2     = (const float*)d_in[11];
    const float* b2     = (const float*)d_in[12];
    const float* l1g    = (const float*)d_in[13];
    const float* l1b    = (const float*)d_in[14];
    const float* l2g    = (const float*)d_in[15];
    const float* l2b    = (const float*)d_in[16];
    const float* wfc    = (const float*)d_in[17];
    const float* bfc    = (const float*)d_in[18];
    float* out = (float*)d_out;

    eeg_init_pe_kernel<<<(TR * DM + 127) / 128, 128>>>();
    eeg_mean_kernel<<<(BB * TT + 255) / 256, 256>>>(x);
    eeg_buildext_kernel<<<(TE * NROWS + 255) / 256, 256>>>(x);
    eeg_fA_kernel<<<dim3(NROWS / 32, CH), 32>>>();
    eeg_fC_kernel<<<dim3(NROWS / 32, CH - 1), 32>>>();
    eeg_bA_kernel<<<dim3(NROWS / 32, CH), 32>>>();
    eeg_bC_kernel<<<dim3(NROWS / 32, CH - 1), 32>>>();
    eeg_resample_kernel<<<NROWS, 256>>>();
    eeg_convqkv_kernel<<<(BB * TR + 255) / 256, 256>>>(conv_w, conv_b, ln0g, ln0b, wqkv, bqkv);
    eeg_attn_kernel<<<NROWS, 128>>>(wo, bo, w1, b1, w2, b2, l1g, l1b, l2g, l2b);
    eeg_head_kernel<<<1, 64>>>(wfc, bfc, out);
}